// round 1
// baseline (speedup 1.0000x reference)
#include <cuda_runtime.h>
#include <cuda_bf16.h>
#include <math.h>

#define B_  32
#define CI_ 128
#define CO_ 256
#define H_  64
#define W_  64
#define E_  8
#define HW_ 4096
#define CC  8   // ci chunk for conv smem staging

// ---------------- scratch (global device arrays; no allocation) ----------------
__device__ float g_pooled[B_ * CI_];                 // mean over HW of x
__device__ float g_rw[B_ * E_];                      // routing weights (softmax)
__device__ float g_w[(size_t)B_ * CI_ * 9 * CO_];    // combined per-sample weights [b][ci][k][co]  (37.7 MB)
__device__ float g_pp[B_ * 4 * 16 * 64];             // per-CTA output-pool partials [b][coTile][sp][coLocal]
__device__ float g_ca[B_ * CO_];                     // channel attention

// ---------------- K1: pool x over HW ----------------
__global__ void pool_x_kernel(const float* __restrict__ x) {
    int bc = blockIdx.x;                 // b*CI + ci
    const float* p = x + (size_t)bc * HW_;
    float s = 0.f;
    for (int i = threadIdx.x; i < HW_; i += 256) s += p[i];
    __shared__ float sm[256];
    sm[threadIdx.x] = s;
    __syncthreads();
    for (int off = 128; off > 0; off >>= 1) {
        if (threadIdx.x < off) sm[threadIdx.x] += sm[threadIdx.x + off];
        __syncthreads();
    }
    if (threadIdx.x == 0) g_pooled[bc] = sm[0] * (1.f / (float)HW_);
}

// ---------------- K2: routing MLP + softmax ----------------
__global__ void routing_kernel(const float* __restrict__ rw1, const float* __restrict__ rb1,
                               const float* __restrict__ rw2, const float* __restrict__ rb2,
                               const float* __restrict__ rw3, const float* __restrict__ rb3) {
    int b = blockIdx.x;
    int t = threadIdx.x;  // 128
    __shared__ float pl[CI_], h[E_], s[CI_], lg[E_];
    pl[t] = g_pooled[b * CI_ + t];
    __syncthreads();
    if (t < E_) {
        float a = rb1[t];
        for (int i = 0; i < CI_; i++) a += rw1[t * CI_ + i] * pl[i];
        h[t] = fmaxf(a, 0.f);
    }
    __syncthreads();
    {
        float a = rb2[t];
#pragma unroll
        for (int j = 0; j < E_; j++) a += rw2[t * E_ + j] * h[j];
        s[t] = 1.f / (1.f + expf(-a));
    }
    __syncthreads();
    if (t < E_) {
        float a = rb3[t];
        for (int i = 0; i < CI_; i++) a += rw3[t * CI_ + i] * s[i];
        lg[t] = a;
    }
    __syncthreads();
    if (t == 0) {
        float m = lg[0];
        for (int e = 1; e < E_; e++) m = fmaxf(m, lg[e]);
        float den = 0.f, ex[E_];
        for (int e = 0; e < E_; e++) { ex[e] = expf(lg[e] - m); den += ex[e]; }
        float inv = 1.f / den;
        for (int e = 0; e < E_; e++) g_rw[b * E_ + e] = ex[e] * inv;
    }
}

// ---------------- K3: combine expert weights -> g_w[b][ci][k][co] ----------------
__global__ void combine_kernel(const float* __restrict__ experts) {
    int cik = blockIdx.x;          // CI*9 blocks
    int ci = cik / 9, k = cik % 9;
    int co = threadIdx.x;          // 256
    __shared__ float es[E_][CO_];
    __shared__ float rw[B_][E_];
#pragma unroll
    for (int e = 0; e < E_; e++)
        es[e][co] = experts[(((size_t)e * CO_ + co) * CI_ + ci) * 9 + k];
    {
        int i = threadIdx.x;
        if (i < B_ * E_) rw[i / E_][i % E_] = g_rw[i];
    }
    __syncthreads();
#pragma unroll 4
    for (int b = 0; b < B_; b++) {
        float acc = 0.f;
#pragma unroll
        for (int e = 0; e < E_; e++) acc += rw[b][e] * es[e][co];
        g_w[(((size_t)b * CI_ + ci) * 9 + k) * CO_ + co] = acc;
    }
}

// ---------------- K4: per-sample conv, fused output pooling ----------------
// grid: (16 spatial tiles, 4 co tiles, 32 b), block 256
// thread: co_group = tid&7 (8 co), pix_group = tid>>3 (2x4 pixels)
__global__ __launch_bounds__(256) void conv_kernel(const float* __restrict__ x,
                                                   float* __restrict__ out) {
    __shared__ __align__(16) float xs[CC][18][18];
    __shared__ __align__(16) float ws[CC][9][64];

    const int b = blockIdx.z;
    const int co0 = blockIdx.y * 64;
    const int sp = blockIdx.x;
    const int ty0 = (sp >> 2) * 16, tx0 = (sp & 3) * 16;
    const int tid = threadIdx.x;
    const int cg = tid & 7, pg = tid >> 3;
    const int px0 = (pg & 3) * 4, py0 = (pg >> 2) * 2;
    const int cobase = cg * 8;

    unsigned long long acc[4][8];
#pragma unroll
    for (int p = 0; p < 4; p++)
#pragma unroll
        for (int q = 0; q < 8; q++) acc[p][q] = 0ULL;

    const float* xb = x + (size_t)b * CI_ * HW_;
    const float* wb = g_w + (size_t)b * CI_ * 9 * CO_;

    for (int ci0 = 0; ci0 < CI_; ci0 += CC) {
        __syncthreads();
        // stage x with halo (zero-padded)
        for (int i = tid; i < CC * 18 * 18; i += 256) {
            int cl = i / 324;
            int r = i - cl * 324;
            int yy = r / 18;
            int xx = r - yy * 18;
            int gy = ty0 + yy - 1, gx = tx0 + xx - 1;
            float v = 0.f;
            if ((unsigned)gy < (unsigned)H_ && (unsigned)gx < (unsigned)W_)
                v = xb[((size_t)(ci0 + cl) * H_ + gy) * W_ + gx];
            xs[cl][yy][xx] = v;
        }
        // stage weights [cl][k][64co] (coalesced from g_w)
        for (int i = tid; i < CC * 9 * 64; i += 256) {
            int col = i & 63;
            int r = i >> 6;
            int k = r % 9;
            int cl = r / 9;
            ws[cl][k][col] = wb[((size_t)(ci0 + cl) * 9 + k) * CO_ + co0 + col];
        }
        __syncthreads();

#pragma unroll 1
        for (int cl = 0; cl < CC; ++cl) {
            float xv[4][6];
#pragma unroll
            for (int ry = 0; ry < 4; ry++)
#pragma unroll
                for (int rx = 0; rx < 6; rx++)
                    xv[ry][rx] = xs[cl][py0 + ry][px0 + rx];
#pragma unroll
            for (int kh = 0; kh < 3; kh++)
#pragma unroll
                for (int kw = 0; kw < 3; kw++) {
                    unsigned long long w2[4];
#pragma unroll
                    for (int p = 0; p < 4; p++)
                        w2[p] = *reinterpret_cast<const unsigned long long*>(
                            &ws[cl][kh * 3 + kw][cobase + 2 * p]);
#pragma unroll
                    for (int dy = 0; dy < 2; dy++)
#pragma unroll
                        for (int dx = 0; dx < 4; dx++) {
                            float xvv = xv[dy + kh][dx + kw];
                            unsigned long long xp;
                            asm("mov.b64 %0, {%1, %1};"
                                : "=l"(xp)
                                : "r"(__float_as_uint(xvv)));
#pragma unroll
                            for (int p = 0; p < 4; p++)
                                asm("fma.rn.f32x2 %0, %1, %2, %0;"
                                    : "+l"(acc[p][dy * 4 + dx])
                                    : "l"(w2[p]), "l"(xp));
                        }
                }
        }
    }

    // epilogue: write outputs + per-co pixel sums
    float* ob = out + ((size_t)b * CO_ + co0) * HW_;
    float cosum[8];
#pragma unroll
    for (int p = 0; p < 4; p++) {
        float s0 = 0.f, s1 = 0.f;
#pragma unroll
        for (int dy = 0; dy < 2; dy++)
#pragma unroll
            for (int dx = 0; dx < 4; dx++) {
                unsigned long long a = acc[p][dy * 4 + dx];
                float lo = __uint_as_float((unsigned)(a & 0xffffffffULL));
                float hi = __uint_as_float((unsigned)(a >> 32));
                int y = ty0 + py0 + dy;
                int xc = tx0 + px0 + dx;
                int col = cobase + 2 * p;
                ob[(size_t)col * HW_ + y * W_ + xc] = lo;
                ob[(size_t)(col + 1) * HW_ + y * W_ + xc] = hi;
                s0 += lo;
                s1 += hi;
            }
        cosum[2 * p] = s0;
        cosum[2 * p + 1] = s1;
    }

    // deterministic pooling partials: reduce 32 pix-groups per co via smem
    __syncthreads();
    float* red = &xs[0][0][0];  // 64*32 = 2048 floats, fits
#pragma unroll
    for (int j = 0; j < 8; j++) red[(cobase + j) * 32 + pg] = cosum[j];
    __syncthreads();
    if (tid < 64) {
        float s = 0.f;
#pragma unroll
        for (int g = 0; g < 32; g++) s += red[tid * 32 + g];
        g_pp[((b * 4 + blockIdx.y) * 16 + blockIdx.x) * 64 + tid] = s;
    }
}

// ---------------- K5: channel attention MLP ----------------
__global__ void attn_kernel(const float* __restrict__ aw1, const float* __restrict__ ab1,
                            const float* __restrict__ aw2, const float* __restrict__ ab2) {
    int b = blockIdx.x;
    int t = threadIdx.x;  // 256
    __shared__ float pm[CO_], hh[16];
    {
        int coTile = t >> 6, colocal = t & 63;
        float s = 0.f;
#pragma unroll
        for (int sp = 0; sp < 16; sp++)
            s += g_pp[((b * 4 + coTile) * 16 + sp) * 64 + colocal];
        pm[t] = s * (1.f / (float)HW_);
    }
    __syncthreads();
    if (t < 16) {
        float a = ab1[t];
        for (int i = 0; i < CO_; i++) a += aw1[t * CO_ + i] * pm[i];
        hh[t] = fmaxf(a, 0.f);
    }
    __syncthreads();
    float a = ab2[t];
#pragma unroll
    for (int j = 0; j < 16; j++) a += aw2[t * 16 + j] * hh[j];
    g_ca[b * CO_ + t] = 1.f / (1.f + expf(-a));
}

// ---------------- K6: in-place output scaling ----------------
__global__ void scale_kernel(float* __restrict__ out) {
    size_t i = (size_t)blockIdx.x * 256 + threadIdx.x;  // float4 index
    float4* o4 = (float4*)out;
    size_t plane = i >> 10;  // 1024 float4 per (b,co) plane
    float c = g_ca[plane];
    float4 v = o4[i];
    v.x *= c; v.y *= c; v.z *= c; v.w *= c;
    o4[i] = v;
}

// ---------------- launch ----------------
extern "C" void kernel_launch(void* const* d_in, const int* in_sizes, int n_in,
                              void* d_out, int out_size) {
    const float* x       = (const float*)d_in[0];
    const float* experts = (const float*)d_in[1];
    const float* rw1 = (const float*)d_in[2];
    const float* rb1 = (const float*)d_in[3];
    const float* rw2 = (const float*)d_in[4];
    const float* rb2 = (const float*)d_in[5];
    const float* rw3 = (const float*)d_in[6];
    const float* rb3 = (const float*)d_in[7];
    const float* aw1 = (const float*)d_in[8];
    const float* ab1 = (const float*)d_in[9];
    const float* aw2 = (const float*)d_in[10];
    const float* ab2 = (const float*)d_in[11];
    float* out = (float*)d_out;

    pool_x_kernel<<<B_ * CI_, 256>>>(x);
    routing_kernel<<<B_, 128>>>(rw1, rb1, rw2, rb2, rw3, rb3);
    combine_kernel<<<CI_ * 9, 256>>>(experts);
    conv_kernel<<<dim3(16, 4, B_), 256>>>(x, out);
    attn_kernel<<<B_, 256>>>(aw1, ab1, aw2, ab2);
    scale_kernel<<<(B_ * CO_ * HW_ / 4) / 256, 256>>>(out);
}

// round 3
// speedup vs baseline: 2.2072x; 2.2072x over previous
#include <cuda_runtime.h>
#include <cuda_bf16.h>
#include <math.h>
#include <stdint.h>

#define B_  32
#define CI_ 128
#define CO_ 256
#define H_  64
#define W_  64
#define E_  8
#define HW_ 4096

// ---------------- scratch ----------------
__device__ float g_pooled[B_ * CI_];
__device__ float g_rw[B_ * E_];
__device__ __nv_bfloat16 g_wh[(size_t)B_ * 9 * CO_ * CI_];  // [b][r][co][ci] hi
__device__ __nv_bfloat16 g_wl[(size_t)B_ * 9 * CO_ * CI_];  // [b][r][co][ci] lo
__device__ float g_pp[(size_t)B_ * 32 * CO_];               // [b][tile][co]
__device__ float g_ca[B_ * CO_];

// ---------------- PTX helpers (base sm_103 PTX only: no 'a' features) -------
__device__ __forceinline__ uint32_t smem_u32(const void* p) {
    uint32_t a;
    asm("{ .reg .u64 t; cvta.to.shared.u64 t, %1; cvt.u32.u64 %0, t; }" : "=r"(a) : "l"(p));
    return a;
}
__device__ __forceinline__ void ldsm4(uint32_t* r, uint32_t addr) {
    asm volatile("ldmatrix.sync.aligned.m8n8.x4.shared.b16 {%0,%1,%2,%3}, [%4];"
                 : "=r"(r[0]), "=r"(r[1]), "=r"(r[2]), "=r"(r[3]) : "r"(addr));
}
__device__ __forceinline__ void ldsm2(uint32_t* r, uint32_t addr) {
    asm volatile("ldmatrix.sync.aligned.m8n8.x2.shared.b16 {%0,%1}, [%2];"
                 : "=r"(r[0]), "=r"(r[1]) : "r"(addr));
}
__device__ __forceinline__ void mma_bf16(float* d, const uint32_t* a, const uint32_t* b) {
    asm volatile(
        "mma.sync.aligned.m16n8k16.row.col.f32.bf16.bf16.f32 "
        "{%0,%1,%2,%3}, {%4,%5,%6,%7}, {%8,%9}, {%0,%1,%2,%3};"
        : "+f"(d[0]), "+f"(d[1]), "+f"(d[2]), "+f"(d[3])
        : "r"(a[0]), "r"(a[1]), "r"(a[2]), "r"(a[3]), "r"(b[0]), "r"(b[1]));
}
__device__ __forceinline__ void cp16(uint32_t dst, const void* src) {
    asm volatile("cp.async.cg.shared.global [%0], [%1], 16;" :: "r"(dst), "l"(src) : "memory");
}
#define CP_COMMIT() asm volatile("cp.async.commit_group;" ::: "memory")
#define CP_WAIT0()  asm volatile("cp.async.wait_group 0;" ::: "memory")

// ---------------- K1: pool x over HW ----------------
__global__ void pool_x_kernel(const float* __restrict__ x) {
    int bc = blockIdx.x;
    const float* p = x + (size_t)bc * HW_;
    float s = 0.f;
    for (int i = threadIdx.x; i < HW_; i += 256) s += p[i];
    __shared__ float sm[256];
    sm[threadIdx.x] = s;
    __syncthreads();
    for (int off = 128; off > 0; off >>= 1) {
        if (threadIdx.x < off) sm[threadIdx.x] += sm[threadIdx.x + off];
        __syncthreads();
    }
    if (threadIdx.x == 0) g_pooled[bc] = sm[0] * (1.f / (float)HW_);
}

// ---------------- K2: routing MLP + softmax ----------------
__global__ void routing_kernel(const float* __restrict__ rw1, const float* __restrict__ rb1,
                               const float* __restrict__ rw2, const float* __restrict__ rb2,
                               const float* __restrict__ rw3, const float* __restrict__ rb3) {
    int b = blockIdx.x;
    int t = threadIdx.x;  // 128
    __shared__ float pl[CI_], h[E_], s[CI_], lg[E_];
    pl[t] = g_pooled[b * CI_ + t];
    __syncthreads();
    if (t < E_) {
        float a = rb1[t];
        for (int i = 0; i < CI_; i++) a += rw1[t * CI_ + i] * pl[i];
        h[t] = fmaxf(a, 0.f);
    }
    __syncthreads();
    {
        float a = rb2[t];
#pragma unroll
        for (int j = 0; j < E_; j++) a += rw2[t * E_ + j] * h[j];
        s[t] = 1.f / (1.f + expf(-a));
    }
    __syncthreads();
    if (t < E_) {
        float a = rb3[t];
        for (int i = 0; i < CI_; i++) a += rw3[t * CI_ + i] * s[i];
        lg[t] = a;
    }
    __syncthreads();
    if (t == 0) {
        float m = lg[0];
        for (int e = 1; e < E_; e++) m = fmaxf(m, lg[e]);
        float den = 0.f, ex[E_];
        for (int e = 0; e < E_; e++) { ex[e] = expf(lg[e] - m); den += ex[e]; }
        float inv = 1.f / den;
        for (int e = 0; e < E_; e++) g_rw[b * E_ + e] = ex[e] * inv;
    }
}

// ---------------- K3: combine experts -> bf16 hi/lo [b][r][co][ci] -----------
__global__ void combine_kernel(const float* __restrict__ experts) {
    int co = blockIdx.x;   // 256
    int ci = threadIdx.x;  // 128
    __shared__ float rws[B_ * E_];
    rws[ci] = g_rw[ci];
    rws[ci + 128] = g_rw[ci + 128];
    __syncthreads();
    float ex[E_ * 9];
#pragma unroll
    for (int e = 0; e < E_; e++) {
        const float* p = experts + (((size_t)e * CO_ + co) * CI_ + ci) * 9;
#pragma unroll
        for (int r = 0; r < 9; r++) ex[e * 9 + r] = p[r];
    }
    for (int b = 0; b < B_; b++) {
#pragma unroll
        for (int r = 0; r < 9; r++) {
            float acc = 0.f;
#pragma unroll
            for (int e = 0; e < E_; e++) acc += rws[b * E_ + e] * ex[e * 9 + r];
            __nv_bfloat16 hi = __float2bfloat16(acc);
            __nv_bfloat16 lo = __float2bfloat16(acc - __bfloat162float(hi));
            size_t idx = ((size_t)(b * 9 + r) * CO_ + co) * CI_ + ci;
            g_wh[idx] = hi;
            g_wl[idx] = lo;
        }
    }
}

// ---------------- K4: implicit-GEMM conv via warp HMMA (bf16 hi/lo, 3-MMA) ---
// grid (32 pixel-tiles, 32 b), 512 threads (16 warps, 4x4 warp grid, 32x64 tile)
// M=128 pixels, N=256 co, K=1152 in 18 stages of 64 ci, double-buffered SMEM.
#define OFF_AH 0
#define OFF_AL 16384
#define OFF_BH 32768
#define OFF_BL 65536
#define BUFB   98304
#define SMEM_TOTAL (2 * BUFB)  // 196608

__global__ __launch_bounds__(512, 1) void conv_mma_kernel(const float* __restrict__ x,
                                                          float* __restrict__ out) {
    extern __shared__ char smem[];
    const uint32_t sb = smem_u32(smem);
    const int tid = threadIdx.x;
    const int wid = tid >> 5;
    const int lane = tid & 31;
    const int tile = blockIdx.x;
    const int b = blockIdx.y;
    const int warp_m = wid & 3;   // 0..3 -> pixel 32-chunk
    const int warp_n = wid >> 2;  // 0..3 -> co 64-chunk

    const float* xb = x + (size_t)b * CI_ * HW_;
    const __nv_bfloat16* wbh = g_wh + (size_t)b * 9 * CO_ * CI_;
    const __nv_bfloat16* wbl = g_wl + (size_t)b * 9 * CO_ * CI_;

    // A-staging thread mapping: p = pixel, cseg = which 16-ci segment
    const int p = tid & 127;
    const int cseg = tid >> 7;  // 0..3
    const int py = tile * 2 + (p >> 6);
    const int px = p & 63;

    float d[2][8][4];
#pragma unroll
    for (int i = 0; i < 2; i++)
#pragma unroll
        for (int j = 0; j < 8; j++)
#pragma unroll
            for (int q = 0; q < 4; q++) d[i][j][q] = 0.f;

    // ---- stage helpers (inlined via lambdas) ----
    auto stageB = [&](int s) {
        const int r = s >> 1;
        const int ci0 = (s & 1) * 64;
        const uint32_t base = sb + (s & 1) * BUFB;
        const __nv_bfloat16* srch = wbh + (size_t)r * CO_ * CI_ + ci0;
        const __nv_bfloat16* srcl = wbl + (size_t)r * CO_ * CI_ + ci0;
#pragma unroll
        for (int it = 0; it < 4; it++) {
            int u = tid + it * 512;
            int row = u >> 3;          // co
            int c = (u & 7) * 16;      // 16B slot in 128B row
            uint32_t sw = (uint32_t)(c ^ ((row & 7) << 4));
            uint32_t doff = (uint32_t)(row * 128) + sw;
            cp16(base + OFF_BH + doff, (const char*)srch + (size_t)row * 256 + c);
            cp16(base + OFF_BL + doff, (const char*)srcl + (size_t)row * 256 + c);
        }
        CP_COMMIT();
    };

    // ---- prologue: stage 0 ----
    {
        stageB(0);
        // A stage 0 (r=0 -> kh=0, kw=0 -> gy=py-1, gx=px-1)
        const int gy = py - 1, gx = px - 1;
        const bool valid = ((unsigned)gy < (unsigned)H_) && ((unsigned)gx < (unsigned)W_);
        const float* xrow = xb + gy * W_ + gx;
        const uint32_t rb8 = (uint32_t)(p * 128);
        const uint32_t swp = (uint32_t)((p & 7) << 4);
#pragma unroll
        for (int i = 0; i < 8; i++) {
            int cil = cseg * 16 + i * 2;
            float v0 = 0.f, v1 = 0.f;
            if (valid) {
                v0 = xrow[(size_t)cil * HW_];
                v1 = xrow[(size_t)(cil + 1) * HW_];
            }
            __nv_bfloat16 h0 = __float2bfloat16(v0), h1 = __float2bfloat16(v1);
            __nv_bfloat16 l0 = __float2bfloat16(v0 - __bfloat162float(h0));
            __nv_bfloat16 l1 = __float2bfloat16(v1 - __bfloat162float(h1));
            uint32_t c = (uint32_t)(cil * 2);
            uint32_t off = rb8 + (c ^ swp);
            *(__nv_bfloat162*)(smem + OFF_AH + off) = __halves2bfloat162(h0, h1);
            *(__nv_bfloat162*)(smem + OFF_AL + off) = __halves2bfloat162(l0, l1);
        }
    }

    // ---- per-lane ldmatrix address components ----
    // A x4: tile t = lane>>3, rl = lane&7
    const int a_t = lane >> 3, a_rl = lane & 7;
    // B x2: ll = lane&15
    const int b_t = (lane & 15) >> 3, b_rl = lane & 7;

    for (int s = 0; s < 18; s++) {
        CP_WAIT0();
        __syncthreads();

        const uint32_t cur = sb + (s & 1) * BUFB;

        // ---- issue next-stage staging (B via cp.async, A LDGs into regs) ----
        float va[16];
        bool do_next = (s < 17);
        const float* xrow_n = xb;
        int ci0n = 0;
        bool validn = false;
        if (do_next) {
            stageB(s + 1);
            const int rn = (s + 1) >> 1;
            ci0n = ((s + 1) & 1) * 64;
            const int kh = rn / 3, kw = rn - kh * 3;
            const int gy = py + kh - 1, gx = px + kw - 1;
            validn = ((unsigned)gy < (unsigned)H_) && ((unsigned)gx < (unsigned)W_);
            xrow_n = xb + gy * W_ + gx;
#pragma unroll
            for (int i = 0; i < 16; i++) {
                int ci = ci0n + cseg * 16 + i;
                va[i] = validn ? xrow_n[(size_t)ci * HW_] : 0.f;
            }
        }

        // ---- MMA over current buffer: 4 k16 chunks ----
#pragma unroll
        for (int kc = 0; kc < 4; kc++) {
            uint32_t ah[2][4], al[2][4];
#pragma unroll
            for (int mi = 0; mi < 2; mi++) {
                int m = warp_m * 32 + mi * 16 + (a_t & 1) * 8 + a_rl;
                int c = kc * 32 + (a_t >> 1) * 16;
                uint32_t addr = cur + (uint32_t)(m * 128 + (c ^ (a_rl << 4)));
                ldsm4(ah[mi], addr + OFF_AH);
                ldsm4(al[mi], addr + OFF_AL);
            }
#pragma unroll
            for (int half = 0; half < 2; half++) {
                uint32_t bh[4][2], bl[4][2];
#pragma unroll
                for (int nj = 0; nj < 4; nj++) {
                    int ni = half * 4 + nj;
                    int n = warp_n * 64 + ni * 8 + b_rl;
                    int c = kc * 32 + b_t * 16;
                    uint32_t addr = cur + (uint32_t)(n * 128 + (c ^ (b_rl << 4)));
                    ldsm2(bh[nj], addr + OFF_BH);
                    ldsm2(bl[nj], addr + OFF_BL);
                }
#pragma unroll
                for (int nj = 0; nj < 4; nj++)
#pragma unroll
                    for (int mi = 0; mi < 2; mi++) {
                        float* acc = d[mi][half * 4 + nj];
                        mma_bf16(acc, ah[mi], bh[nj]);
                        mma_bf16(acc, ah[mi], bl[nj]);
                        mma_bf16(acc, al[mi], bh[nj]);
                    }
            }
        }

        // ---- convert + store A(s+1) ----
        if (do_next) {
            const uint32_t nb = (uint32_t)(((s + 1) & 1) * BUFB);
            const uint32_t rb8 = (uint32_t)(p * 128);
            const uint32_t swp = (uint32_t)((p & 7) << 4);
#pragma unroll
            for (int i = 0; i < 8; i++) {
                float v0 = va[2 * i], v1 = va[2 * i + 1];
                __nv_bfloat16 h0 = __float2bfloat16(v0), h1 = __float2bfloat16(v1);
                __nv_bfloat16 l0 = __float2bfloat16(v0 - __bfloat162float(h0));
                __nv_bfloat16 l1 = __float2bfloat16(v1 - __bfloat162float(h1));
                int cil = cseg * 16 + i * 2;
                uint32_t c = (uint32_t)(cil * 2);
                uint32_t off = rb8 + (c ^ swp);
                *(__nv_bfloat162*)(smem + nb + OFF_AH + off) = __halves2bfloat162(h0, h1);
                *(__nv_bfloat162*)(smem + nb + OFF_AL + off) = __halves2bfloat162(l0, l1);
            }
        }
    }

    // ---- epilogue: transpose through smem, coalesced writes + pooling ----
    __syncthreads();
    float* red = (float*)smem;  // [256 co][132] floats = 135168 B
#pragma unroll
    for (int mi = 0; mi < 2; mi++)
#pragma unroll
        for (int ni = 0; ni < 8; ni++) {
            int m = warp_m * 32 + mi * 16 + (lane >> 2);
            int n = warp_n * 64 + ni * 8 + 2 * (lane & 3);
            const float* a = d[mi][ni];
            red[n * 132 + m] = a[0];
            red[(n + 1) * 132 + m] = a[1];
            red[n * 132 + m + 8] = a[2];
            red[(n + 1) * 132 + m + 8] = a[3];
        }
    __syncthreads();
    {
        int co = tid >> 1, half = tid & 1;
        const float4* rp = (const float4*)(red + co * 132 + half * 64);
        float* op = out + ((size_t)(b * CO_ + co)) * HW_ + tile * 128 + half * 64;
        float s = 0.f;
#pragma unroll
        for (int i = 0; i < 16; i++) {
            float4 v = rp[i];
            ((float4*)op)[i] = v;
            s += v.x + v.y + v.z + v.w;
        }
        float tot = s + __shfl_xor_sync(0xffffffffu, s, 1);
        if (half == 0) g_pp[((size_t)b * 32 + tile) * CO_ + co] = tot;
    }
}

// ---------------- K5: channel attention MLP ----------------
__global__ void attn_kernel(const float* __restrict__ aw1, const float* __restrict__ ab1,
                            const float* __restrict__ aw2, const float* __restrict__ ab2) {
    int b = blockIdx.x;
    int t = threadIdx.x;  // 256
    __shared__ float pm[CO_], hh[16];
    {
        float s = 0.f;
#pragma unroll
        for (int i = 0; i < 32; i++) s += g_pp[((size_t)b * 32 + i) * CO_ + t];
        pm[t] = s * (1.f / (float)HW_);
    }
    __syncthreads();
    if (t < 16) {
        float a = ab1[t];
        for (int i = 0; i < CO_; i++) a += aw1[t * CO_ + i] * pm[i];
        hh[t] = fmaxf(a, 0.f);
    }
    __syncthreads();
    float a = ab2[t];
#pragma unroll
    for (int j = 0; j < 16; j++) a += aw2[t * 16 + j] * hh[j];
    g_ca[b * CO_ + t] = 1.f / (1.f + expf(-a));
}

// ---------------- K6: in-place output scaling ----------------
__global__ void scale_kernel(float* __restrict__ out) {
    size_t i = (size_t)blockIdx.x * 256 + threadIdx.x;  // float4 index
    float4* o4 = (float4*)out;
    size_t plane = i >> 10;
    float c = g_ca[plane];
    float4 v = o4[i];
    v.x *= c; v.y *= c; v.z *= c; v.w *= c;
    o4[i] = v;
}

// ---------------- launch ----------------
extern "C" void kernel_launch(void* const* d_in, const int* in_sizes, int n_in,
                              void* d_out, int out_size) {
    const float* x       = (const float*)d_in[0];
    const float* experts = (const float*)d_in[1];
    const float* rw1 = (const float*)d_in[2];
    const float* rb1 = (const float*)d_in[3];
    const float* rw2 = (const float*)d_in[4];
    const float* rb2 = (const float*)d_in[5];
    const float* rw3 = (const float*)d_in[6];
    const float* rb3 = (const float*)d_in[7];
    const float* aw1 = (const float*)d_in[8];
    const float* ab1 = (const float*)d_in[9];
    const float* aw2 = (const float*)d_in[10];
    const float* ab2 = (const float*)d_in[11];
    float* out = (float*)d_out;

    cudaFuncSetAttribute(conv_mma_kernel, cudaFuncAttributeMaxDynamicSharedMemorySize,
                         SMEM_TOTAL);

    pool_x_kernel<<<B_ * CI_, 256>>>(x);
    routing_kernel<<<B_, 128>>>(rw1, rb1, rw2, rb2, rw3, rb3);
    combine_kernel<<<CO_, 128>>>(experts);
    conv_mma_kernel<<<dim3(32, B_), 512, SMEM_TOTAL>>>(x, out);
    attn_kernel<<<B_, 256>>>(aw1, ab1, aw2, ab2);
    scale_kernel<<<(B_ * CO_ * HW_ / 4) / 256, 256>>>(out);
}

// round 4
// speedup vs baseline: 3.2967x; 1.4936x over previous
#include <cuda_runtime.h>
#include <cuda_fp16.h>
#include <math.h>
#include <stdint.h>

#define B_  32
#define CI_ 128
#define CO_ 256
#define H_  64
#define W_  64
#define E_  8
#define HW_ 4096
#define XROWS 66
#define XPLANE (XROWS * 64)   // 4224 halves per (kw,b,ci)

// ---------------- scratch ----------------
__device__ float g_pooled[B_ * CI_];
__device__ float g_rw[B_ * E_];
__device__ __half g_x3[(size_t)3 * B_ * CI_ * XPLANE];      // kw-shifted, halo-padded x (fp16)
__device__ __half g_wh[(size_t)B_ * 9 * CO_ * CI_];         // [b][r][co][ci] hi
__device__ __half g_wl[(size_t)B_ * 9 * CO_ * CI_];         // [b][r][co][ci] lo
__device__ float g_pp[(size_t)B_ * 32 * CO_];               // [b][tile][co]
__device__ float g_ca[B_ * CO_];

// ---------------- PTX helpers (base sm_103 PTX only) ----------------
__device__ __forceinline__ uint32_t smem_u32(const void* p) {
    uint32_t a;
    asm("{ .reg .u64 t; cvta.to.shared.u64 t, %1; cvt.u32.u64 %0, t; }" : "=r"(a) : "l"(p));
    return a;
}
__device__ __forceinline__ void ldsm4(uint32_t* r, uint32_t addr) {
    asm volatile("ldmatrix.sync.aligned.m8n8.x4.shared.b16 {%0,%1,%2,%3}, [%4];"
                 : "=r"(r[0]), "=r"(r[1]), "=r"(r[2]), "=r"(r[3]) : "r"(addr));
}
__device__ __forceinline__ void ldsm4t(uint32_t* r, uint32_t addr) {
    asm volatile("ldmatrix.sync.aligned.m8n8.x4.trans.shared.b16 {%0,%1,%2,%3}, [%4];"
                 : "=r"(r[0]), "=r"(r[1]), "=r"(r[2]), "=r"(r[3]) : "r"(addr));
}
__device__ __forceinline__ void mma_f16(float* d, const uint32_t* a, const uint32_t* b) {
    asm volatile(
        "mma.sync.aligned.m16n8k16.row.col.f32.f16.f16.f32 "
        "{%0,%1,%2,%3}, {%4,%5,%6,%7}, {%8,%9}, {%0,%1,%2,%3};"
        : "+f"(d[0]), "+f"(d[1]), "+f"(d[2]), "+f"(d[3])
        : "r"(a[0]), "r"(a[1]), "r"(a[2]), "r"(a[3]), "r"(b[0]), "r"(b[1]));
}
__device__ __forceinline__ void cp16(uint32_t dst, const void* src) {
    asm volatile("cp.async.cg.shared.global [%0], [%1], 16;" :: "r"(dst), "l"(src) : "memory");
}
#define CP_COMMIT() asm volatile("cp.async.commit_group;" ::: "memory")
#define CP_WAIT0()  asm volatile("cp.async.wait_group 0;" ::: "memory")

// ---------------- K1: x -> fp16 shifted copies + pooled mean ----------------
__global__ __launch_bounds__(256) void xprep_kernel(const float* __restrict__ x) {
    const int bc = blockIdx.x;             // b*CI + ci
    const int b = bc >> 7, ci = bc & 127;
    const int tid = threadIdx.x;
    __shared__ float xp[HW_];
    __shared__ float rs[256];
    const float* src = x + (size_t)bc * HW_;
    float s = 0.f;
    for (int i = tid; i < HW_; i += 256) {
        float v = src[i];
        xp[i] = v;
        s += v;
    }
    rs[tid] = s;
    __syncthreads();
    for (int off = 128; off > 0; off >>= 1) {
        if (tid < off) rs[tid] += rs[tid + off];
        __syncthreads();
    }
    if (tid == 0) g_pooled[bc] = rs[0] * (1.f / (float)HW_);

#pragma unroll
    for (int kw = 0; kw < 3; kw++) {
        __half2* dst = (__half2*)(g_x3 + ((size_t)(kw * B_ + b) * CI_ + ci) * XPLANE);
        for (int idx = tid; idx < XROWS * 32; idx += 256) {
            int row = idx >> 5;            // 0..65 (= gy+1)
            int px = (idx & 31) * 2;
            int gy = row - 1;
            float v0 = 0.f, v1 = 0.f;
            if ((unsigned)gy < (unsigned)H_) {
                int gx0 = px + kw - 1;
                int gx1 = gx0 + 1;
                if ((unsigned)gx0 < (unsigned)W_) v0 = xp[gy * 64 + gx0];
                if ((unsigned)gx1 < (unsigned)W_) v1 = xp[gy * 64 + gx1];
            }
            dst[idx] = __floats2half2_rn(v0, v1);
        }
    }
}

// ---------------- K2: routing MLP + softmax ----------------
__global__ void routing_kernel(const float* __restrict__ rw1, const float* __restrict__ rb1,
                               const float* __restrict__ rw2, const float* __restrict__ rb2,
                               const float* __restrict__ rw3, const float* __restrict__ rb3) {
    int b = blockIdx.x;
    int t = threadIdx.x;  // 128
    __shared__ float pl[CI_], h[E_], s[CI_], lg[E_];
    pl[t] = g_pooled[b * CI_ + t];
    __syncthreads();
    if (t < E_) {
        float a = rb1[t];
        for (int i = 0; i < CI_; i++) a += rw1[t * CI_ + i] * pl[i];
        h[t] = fmaxf(a, 0.f);
    }
    __syncthreads();
    {
        float a = rb2[t];
#pragma unroll
        for (int j = 0; j < E_; j++) a += rw2[t * E_ + j] * h[j];
        s[t] = 1.f / (1.f + expf(-a));
    }
    __syncthreads();
    if (t < E_) {
        float a = rb3[t];
        for (int i = 0; i < CI_; i++) a += rw3[t * CI_ + i] * s[i];
        lg[t] = a;
    }
    __syncthreads();
    if (t == 0) {
        float m = lg[0];
        for (int e = 1; e < E_; e++) m = fmaxf(m, lg[e]);
        float den = 0.f, ex[E_];
        for (int e = 0; e < E_; e++) { ex[e] = expf(lg[e] - m); den += ex[e]; }
        float inv = 1.f / den;
        for (int e = 0; e < E_; e++) g_rw[b * E_ + e] = ex[e] * inv;
    }
}

// ---------------- K3: combine experts -> fp16 hi/lo [b][r][co][ci] -----------
__global__ void combine_kernel(const float* __restrict__ experts) {
    int co = blockIdx.x;   // 256
    int ci = threadIdx.x;  // 128
    __shared__ float rws[B_ * E_];
    rws[ci] = g_rw[ci];
    rws[ci + 128] = g_rw[ci + 128];
    __syncthreads();
    float ex[E_ * 9];
#pragma unroll
    for (int e = 0; e < E_; e++) {
        const float* p = experts + (((size_t)e * CO_ + co) * CI_ + ci) * 9;
#pragma unroll
        for (int r = 0; r < 9; r++) ex[e * 9 + r] = p[r];
    }
    for (int b = 0; b < B_; b++) {
#pragma unroll
        for (int r = 0; r < 9; r++) {
            float acc = 0.f;
#pragma unroll
            for (int e = 0; e < E_; e++) acc += rws[b * E_ + e] * ex[e * 9 + r];
            __half hi = __float2half_rn(acc);
            __half lo = __float2half_rn(acc - __half2float(hi));
            size_t idx = ((size_t)(b * 9 + r) * CO_ + co) * CI_ + ci;
            g_wh[idx] = hi;
            g_wl[idx] = lo;
        }
    }
}

// ---------------- K4: implicit-GEMM conv (fp16 W-hi/lo 2-MMA) ----------------
// grid (32 pixel-tiles, 32 b), 512 threads, warp tile 32x64.
// M=128 pixels, N=256 co, K=1152 over 18 stages of 64 ci, double-buffered.
#define OFF_A  0
#define OFF_BH 16384
#define OFF_BL 49152
#define BUFB   81920
#define SMEM_TOTAL (2 * BUFB)  // 163840

__global__ __launch_bounds__(512, 1) void conv_mma_kernel(float* __restrict__ out) {
    extern __shared__ char smem[];
    const uint32_t sb = smem_u32(smem);
    const int tid = threadIdx.x;
    const int wid = tid >> 5;
    const int lane = tid & 31;
    const int tile = blockIdx.x;
    const int b = blockIdx.y;
    const int warp_m = wid & 3;
    const int warp_n = wid >> 2;

    float d[2][8][4];
#pragma unroll
    for (int i = 0; i < 2; i++)
#pragma unroll
        for (int j = 0; j < 8; j++)
#pragma unroll
            for (int q = 0; q < 4; q++) d[i][j][q] = 0.f;

    const __half* whb = g_wh + (size_t)b * 9 * CO_ * CI_;
    const __half* wlb = g_wl + (size_t)b * 9 * CO_ * CI_;

    auto stage = [&](int s) {
        const int r = s >> 1;
        const int ci0 = (s & 1) * 64;
        const int kh = r / 3, kw = r - kh * 3;
        const uint32_t base = sb + (uint32_t)((s & 1) * BUFB);
        // A: 64 ci rows x 128 px (2 gmem rows) fp16, 16B-aligned contiguous
        const char* asrc = (const char*)(g_x3 + ((size_t)(kw * B_ + b) * CI_ + ci0) * XPLANE +
                                         (size_t)(tile * 2 + kh) * 64);
#pragma unroll
        for (int it = 0; it < 2; it++) {
            int idx = tid + it * 512;
            int ci = idx >> 4, ch = idx & 15;
            cp16(base + OFF_A + (uint32_t)(ci * 256 + ((ch * 16) ^ ((ci & 7) << 4))),
                 asrc + (size_t)ci * (XPLANE * 2) + ch * 16);
        }
        // B: 256 co x 64 ci fp16, hi + lo
        const char* hsrc = (const char*)(whb + (size_t)r * CO_ * CI_ + ci0);
        const char* lsrc = (const char*)(wlb + (size_t)r * CO_ * CI_ + ci0);
#pragma unroll
        for (int it = 0; it < 4; it++) {
            int idx = tid + it * 512;
            int co = idx >> 3, ch = idx & 7;
            uint32_t off = (uint32_t)(co * 128 + ((ch * 16) ^ ((co & 7) << 4)));
            cp16(base + OFF_BH + off, hsrc + (size_t)co * 256 + ch * 16);
            cp16(base + OFF_BL + off, lsrc + (size_t)co * 256 + ch * 16);
        }
        CP_COMMIT();
    };

    stage(0);

    // ldmatrix lane components
    const int a_t = lane >> 3, a_rl = lane & 7;               // A x4 trans
    const int b_q = lane >> 3, b_rl = lane & 7;               // B x4
    const int b_nsel = b_q >> 1, b_ksel = b_q & 1;

    for (int s = 0; s < 18; s++) {
        CP_WAIT0();
        __syncthreads();
        if (s < 17) stage(s + 1);
        const uint32_t cur = sb + (uint32_t)((s & 1) * BUFB);

#pragma unroll
        for (int kc = 0; kc < 4; kc++) {
            uint32_t ah[2][4];
#pragma unroll
            for (int mi = 0; mi < 2; mi++) {
                int k_row = kc * 16 + (a_t >> 1) * 8 + a_rl;
                int m_col = warp_m * 32 + mi * 16 + (a_t & 1) * 8;
                uint32_t addr = cur + OFF_A +
                                (uint32_t)(k_row * 256 + ((m_col * 2) ^ (a_rl << 4)));
                ldsm4t(ah[mi], addr);
            }
#pragma unroll
            for (int njp = 0; njp < 4; njp++) {
                int n = warp_n * 64 + njp * 16 + b_nsel * 8 + b_rl;
                uint32_t kb = (uint32_t)(kc * 32 + b_ksel * 16);
                uint32_t off = (uint32_t)(n * 128) + (kb ^ (uint32_t)(b_rl << 4));
                uint32_t bh[4], bl[4];
                ldsm4(bh, cur + OFF_BH + off);
                ldsm4(bl, cur + OFF_BL + off);
#pragma unroll
                for (int j = 0; j < 2; j++)
#pragma unroll
                    for (int mi = 0; mi < 2; mi++) {
                        float* acc = d[mi][njp * 2 + j];
                        mma_f16(acc, ah[mi], bh + 2 * j);
                        mma_f16(acc, ah[mi], bl + 2 * j);
                    }
            }
        }
    }

    // ---- epilogue: transpose through smem, coalesced writes + pooling ----
    __syncthreads();
    float* red = (float*)smem;  // [256 co][132]
#pragma unroll
    for (int mi = 0; mi < 2; mi++)
#pragma unroll
        for (int ni = 0; ni < 8; ni++) {
            int m = warp_m * 32 + mi * 16 + (lane >> 2);
            int n = warp_n * 64 + ni * 8 + 2 * (lane & 3);
            const float* a = d[mi][ni];
            red[n * 132 + m] = a[0];
            red[(n + 1) * 132 + m] = a[1];
            red[n * 132 + m + 8] = a[2];
            red[(n + 1) * 132 + m + 8] = a[3];
        }
    __syncthreads();
    {
        int co = tid >> 1, half = tid & 1;
        const float4* rp = (const float4*)(red + co * 132 + half * 64);
        float* op = out + ((size_t)(b * CO_ + co)) * HW_ + tile * 128 + half * 64;
        float s = 0.f;
#pragma unroll
        for (int i = 0; i < 16; i++) {
            float4 v = rp[i];
            ((float4*)op)[i] = v;
            s += v.x + v.y + v.z + v.w;
        }
        float tot = s + __shfl_xor_sync(0xffffffffu, s, 1);
        if (half == 0) g_pp[((size_t)b * 32 + tile) * CO_ + co] = tot;
    }
}

// ---------------- K5: channel attention MLP ----------------
__global__ void attn_kernel(const float* __restrict__ aw1, const float* __restrict__ ab1,
                            const float* __restrict__ aw2, const float* __restrict__ ab2) {
    int b = blockIdx.x;
    int t = threadIdx.x;  // 256
    __shared__ float pm[CO_], hh[16];
    {
        float s = 0.f;
#pragma unroll
        for (int i = 0; i < 32; i++) s += g_pp[((size_t)b * 32 + i) * CO_ + t];
        pm[t] = s * (1.f / (float)HW_);
    }
    __syncthreads();
    if (t < 16) {
        float a = ab1[t];
        for (int i = 0; i < CO_; i++) a += aw1[t * CO_ + i] * pm[i];
        hh[t] = fmaxf(a, 0.f);
    }
    __syncthreads();
    float a = ab2[t];
#pragma unroll
    for (int j = 0; j < 16; j++) a += aw2[t * 16 + j] * hh[j];
    g_ca[b * CO_ + t] = 1.f / (1.f + expf(-a));
}

// ---------------- K6: in-place output scaling ----------------
__global__ void scale_kernel(float* __restrict__ out) {
    size_t i = (size_t)blockIdx.x * 256 + threadIdx.x;  // float4 index
    float4* o4 = (float4*)out;
    size_t plane = i >> 10;
    float c = g_ca[plane];
    float4 v = o4[i];
    v.x *= c; v.y *= c; v.z *= c; v.w *= c;
    o4[i] = v;
}

// ---------------- launch ----------------
extern "C" void kernel_launch(void* const* d_in, const int* in_sizes, int n_in,
                              void* d_out, int out_size) {
    const float* x       = (const float*)d_in[0];
    const float* experts = (const float*)d_in[1];
    const float* rw1 = (const float*)d_in[2];
    const float* rb1 = (const float*)d_in[3];
    const float* rw2 = (const float*)d_in[4];
    const float* rb2 = (const float*)d_in[5];
    const float* rw3 = (const float*)d_in[6];
    const float* rb3 = (const float*)d_in[7];
    const float* aw1 = (const float*)d_in[8];
    const float* ab1 = (const float*)d_in[9];
    const float* aw2 = (const float*)d_in[10];
    const float* ab2 = (const float*)d_in[11];
    float* out = (float*)d_out;

    cudaFuncSetAttribute(conv_mma_kernel, cudaFuncAttributeMaxDynamicSharedMemorySize,
                         SMEM_TOTAL);

    xprep_kernel<<<B_ * CI_, 256>>>(x);
    routing_kernel<<<B_, 128>>>(rw1, rb1, rw2, rb2, rw3, rb3);
    combine_kernel<<<CO_, 128>>>(experts);
    conv_mma_kernel<<<dim3(32, B_), 512, SMEM_TOTAL>>>(out);
    attn_kernel<<<B_, 256>>>(aw1, ab1, aw2, ab2);
    scale_kernel<<<(B_ * CO_ * HW_ / 4) / 256, 256>>>(out);
}

// round 5
// speedup vs baseline: 4.5250x; 1.3726x over previous
#include <cuda_runtime.h>
#include <cuda_fp16.h>
#include <math.h>
#include <stdint.h>

#define B_  32
#define CI_ 128
#define CO_ 256
#define H_  64
#define W_  64
#define E_  8
#define HW_ 4096
#define XROWS 66
#define XPLANE (XROWS * 64)   // 4224 halves per (kw,b,ci)

// ---------------- scratch ----------------
__device__ float g_pooled[B_ * CI_];
__device__ float g_rw[B_ * E_];
__device__ __half g_x3[(size_t)3 * B_ * CI_ * XPLANE];      // kw-shifted, halo-padded x (fp16)
__device__ __half g_wh[(size_t)B_ * 9 * CO_ * CI_];         // [b][r][co][ci]
__device__ float g_pp[(size_t)B_ * 32 * CO_];               // [b][tile][co]
__device__ float g_ca[B_ * CO_];

// ---------------- PTX helpers (base sm_103 PTX only) ----------------
__device__ __forceinline__ uint32_t smem_u32(const void* p) {
    uint32_t a;
    asm("{ .reg .u64 t; cvta.to.shared.u64 t, %1; cvt.u32.u64 %0, t; }" : "=r"(a) : "l"(p));
    return a;
}
__device__ __forceinline__ void ldsm4(uint32_t* r, uint32_t addr) {
    asm volatile("ldmatrix.sync.aligned.m8n8.x4.shared.b16 {%0,%1,%2,%3}, [%4];"
                 : "=r"(r[0]), "=r"(r[1]), "=r"(r[2]), "=r"(r[3]) : "r"(addr));
}
__device__ __forceinline__ void ldsm4t(uint32_t* r, uint32_t addr) {
    asm volatile("ldmatrix.sync.aligned.m8n8.x4.trans.shared.b16 {%0,%1,%2,%3}, [%4];"
                 : "=r"(r[0]), "=r"(r[1]), "=r"(r[2]), "=r"(r[3]) : "r"(addr));
}
__device__ __forceinline__ void mma_f16(float* d, const uint32_t* a, const uint32_t* b) {
    asm volatile(
        "mma.sync.aligned.m16n8k16.row.col.f32.f16.f16.f32 "
        "{%0,%1,%2,%3}, {%4,%5,%6,%7}, {%8,%9}, {%0,%1,%2,%3};"
        : "+f"(d[0]), "+f"(d[1]), "+f"(d[2]), "+f"(d[3])
        : "r"(a[0]), "r"(a[1]), "r"(a[2]), "r"(a[3]), "r"(b[0]), "r"(b[1]));
}
__device__ __forceinline__ void cp16(uint32_t dst, const void* src) {
    asm volatile("cp.async.cg.shared.global [%0], [%1], 16;" :: "r"(dst), "l"(src) : "memory");
}
#define CP_COMMIT() asm volatile("cp.async.commit_group;" ::: "memory")
#define CP_WAIT2()  asm volatile("cp.async.wait_group 2;" ::: "memory")

// ---------------- K1: x -> fp16 shifted copies + pooled mean ----------------
__global__ __launch_bounds__(256) void xprep_kernel(const float* __restrict__ x) {
    const int bc = blockIdx.x;             // b*CI + ci
    const int b = bc >> 7, ci = bc & 127;
    const int tid = threadIdx.x;
    __shared__ float xp[HW_];
    __shared__ float rs[256];
    const float* src = x + (size_t)bc * HW_;
    float s = 0.f;
    for (int i = tid; i < HW_; i += 256) {
        float v = src[i];
        xp[i] = v;
        s += v;
    }
    rs[tid] = s;
    __syncthreads();
    for (int off = 128; off > 0; off >>= 1) {
        if (tid < off) rs[tid] += rs[tid + off];
        __syncthreads();
    }
    if (tid == 0) g_pooled[bc] = rs[0] * (1.f / (float)HW_);

#pragma unroll
    for (int kw = 0; kw < 3; kw++) {
        __half2* dst = (__half2*)(g_x3 + ((size_t)(kw * B_ + b) * CI_ + ci) * XPLANE);
        for (int idx = tid; idx < XROWS * 32; idx += 256) {
            int row = idx >> 5;            // 0..65 (= gy+1)
            int px = (idx & 31) * 2;
            int gy = row - 1;
            float v0 = 0.f, v1 = 0.f;
            if ((unsigned)gy < (unsigned)H_) {
                int gx0 = px + kw - 1;
                int gx1 = gx0 + 1;
                if ((unsigned)gx0 < (unsigned)W_) v0 = xp[gy * 64 + gx0];
                if ((unsigned)gx1 < (unsigned)W_) v1 = xp[gy * 64 + gx1];
            }
            dst[idx] = __floats2half2_rn(v0, v1);
        }
    }
}

// ---------------- K2: routing MLP + softmax ----------------
__global__ void routing_kernel(const float* __restrict__ rw1, const float* __restrict__ rb1,
                               const float* __restrict__ rw2, const float* __restrict__ rb2,
                               const float* __restrict__ rw3, const float* __restrict__ rb3) {
    int b = blockIdx.x;
    int t = threadIdx.x;  // 128
    __shared__ float pl[CI_], h[E_], s[CI_], lg[E_];
    pl[t] = g_pooled[b * CI_ + t];
    __syncthreads();
    if (t < E_) {
        float a = rb1[t];
        for (int i = 0; i < CI_; i++) a += rw1[t * CI_ + i] * pl[i];
        h[t] = fmaxf(a, 0.f);
    }
    __syncthreads();
    {
        float a = rb2[t];
#pragma unroll
        for (int j = 0; j < E_; j++) a += rw2[t * E_ + j] * h[j];
        s[t] = 1.f / (1.f + expf(-a));
    }
    __syncthreads();
    if (t < E_) {
        float a = rb3[t];
        for (int i = 0; i < CI_; i++) a += rw3[t * CI_ + i] * s[i];
        lg[t] = a;
    }
    __syncthreads();
    if (t == 0) {
        float m = lg[0];
        for (int e = 1; e < E_; e++) m = fmaxf(m, lg[e]);
        float den = 0.f, ex[E_];
        for (int e = 0; e < E_; e++) { ex[e] = expf(lg[e] - m); den += ex[e]; }
        float inv = 1.f / den;
        for (int e = 0; e < E_; e++) g_rw[b * E_ + e] = ex[e] * inv;
    }
}

// ---------------- K3: combine experts -> fp16 [b][r][co][ci] -----------------
__global__ void combine_kernel(const float* __restrict__ experts) {
    int co = blockIdx.x;   // 256
    int ci = threadIdx.x;  // 128
    __shared__ float rws[B_ * E_];
    rws[ci] = g_rw[ci];
    rws[ci + 128] = g_rw[ci + 128];
    __syncthreads();
    float ex[E_ * 9];
#pragma unroll
    for (int e = 0; e < E_; e++) {
        const float* p = experts + (((size_t)e * CO_ + co) * CI_ + ci) * 9;
#pragma unroll
        for (int r = 0; r < 9; r++) ex[e * 9 + r] = p[r];
    }
    for (int b = 0; b < B_; b++) {
#pragma unroll
        for (int r = 0; r < 9; r++) {
            float acc = 0.f;
#pragma unroll
            for (int e = 0; e < E_; e++) acc += rws[b * E_ + e] * ex[e * 9 + r];
            g_wh[((size_t)(b * 9 + r) * CO_ + co) * CI_ + ci] = __float2half_rn(acc);
        }
    }
}

// ---------------- K4: implicit-GEMM conv (fp16 single MMA, 4-deep pipeline) --
// grid (32 pixel-tiles, 32 b), 512 threads, warp tile 32x64.
// M=128 pixels, N=256 co, K=1152 over 18 stages of 64 ci, 4-stage cp.async ring.
#define OFF_A  0
#define OFF_B  16384
#define BUFB   49152
#define NSTAGE 4
#define SMEM_TOTAL (NSTAGE * BUFB)  // 196608

__global__ __launch_bounds__(512, 1) void conv_mma_kernel(float* __restrict__ out) {
    extern __shared__ char smem[];
    const uint32_t sb = smem_u32(smem);
    const int tid = threadIdx.x;
    const int wid = tid >> 5;
    const int lane = tid & 31;
    const int tile = blockIdx.x;
    const int b = blockIdx.y;
    const int warp_m = wid & 3;
    const int warp_n = wid >> 2;

    float d[2][8][4];
#pragma unroll
    for (int i = 0; i < 2; i++)
#pragma unroll
        for (int j = 0; j < 8; j++)
#pragma unroll
            for (int q = 0; q < 4; q++) d[i][j][q] = 0.f;

    const __half* whb = g_wh + (size_t)b * 9 * CO_ * CI_;

    auto stage = [&](int s) {
        const int r = s >> 1;
        const int ci0 = (s & 1) * 64;
        const int kh = r / 3, kw = r - kh * 3;
        const uint32_t base = sb + (uint32_t)((s & 3) * BUFB);
        // A: 64 ci rows x 128 px (2 gmem rows) fp16
        const char* asrc = (const char*)(g_x3 + ((size_t)(kw * B_ + b) * CI_ + ci0) * XPLANE +
                                         (size_t)(tile * 2 + kh) * 64);
#pragma unroll
        for (int it = 0; it < 2; it++) {
            int idx = tid + it * 512;
            int ci = idx >> 4, ch = idx & 15;
            cp16(base + OFF_A + (uint32_t)(ci * 256 + ((ch * 16) ^ ((ci & 7) << 4))),
                 asrc + (size_t)ci * (XPLANE * 2) + ch * 16);
        }
        // B: 256 co x 64 ci fp16
        const char* hsrc = (const char*)(whb + (size_t)r * CO_ * CI_ + ci0);
#pragma unroll
        for (int it = 0; it < 4; it++) {
            int idx = tid + it * 512;
            int co = idx >> 3, ch = idx & 7;
            uint32_t off = (uint32_t)(co * 128 + ((ch * 16) ^ ((co & 7) << 4)));
            cp16(base + OFF_B + off, hsrc + (size_t)co * 256 + ch * 16);
        }
        CP_COMMIT();
    };

    stage(0);
    stage(1);
    stage(2);

    // ldmatrix lane components
    const int a_t = lane >> 3, a_rl = lane & 7;               // A x4 trans
    const int b_q = lane >> 3, b_rl = lane & 7;               // B x4
    const int b_nsel = b_q >> 1, b_ksel = b_q & 1;

    for (int s = 0; s < 18; s++) {
        CP_WAIT2();
        __syncthreads();
        if (s < 15) stage(s + 3);
        const uint32_t cur = sb + (uint32_t)((s & 3) * BUFB);

#pragma unroll
        for (int kc = 0; kc < 4; kc++) {
            uint32_t ah[2][4];
#pragma unroll
            for (int mi = 0; mi < 2; mi++) {
                int k_row = kc * 16 + (a_t >> 1) * 8 + a_rl;
                int m_col = warp_m * 32 + mi * 16 + (a_t & 1) * 8;
                uint32_t addr = cur + OFF_A +
                                (uint32_t)(k_row * 256 + ((m_col * 2) ^ (a_rl << 4)));
                ldsm4t(ah[mi], addr);
            }
#pragma unroll
            for (int njp = 0; njp < 4; njp++) {
                int n = warp_n * 64 + njp * 16 + b_nsel * 8 + b_rl;
                uint32_t kb = (uint32_t)(kc * 32 + b_ksel * 16);
                uint32_t off = (uint32_t)(n * 128) + (kb ^ (uint32_t)(b_rl << 4));
                uint32_t bh[4];
                ldsm4(bh, cur + OFF_B + off);
#pragma unroll
                for (int j = 0; j < 2; j++)
#pragma unroll
                    for (int mi = 0; mi < 2; mi++)
                        mma_f16(d[mi][njp * 2 + j], ah[mi], bh + 2 * j);
            }
        }
    }

    // ---- epilogue: transpose through smem, coalesced writes + pooling ----
    __syncthreads();
    float* red = (float*)smem;  // [256 co][132]
#pragma unroll
    for (int mi = 0; mi < 2; mi++)
#pragma unroll
        for (int ni = 0; ni < 8; ni++) {
            int m = warp_m * 32 + mi * 16 + (lane >> 2);
            int n = warp_n * 64 + ni * 8 + 2 * (lane & 3);
            const float* a = d[mi][ni];
            red[n * 132 + m] = a[0];
            red[(n + 1) * 132 + m] = a[1];
            red[n * 132 + m + 8] = a[2];
            red[(n + 1) * 132 + m + 8] = a[3];
        }
    __syncthreads();
    {
        int co = tid >> 1, half = tid & 1;
        const float4* rp = (const float4*)(red + co * 132 + half * 64);
        float* op = out + ((size_t)(b * CO_ + co)) * HW_ + tile * 128 + half * 64;
        float s = 0.f;
#pragma unroll
        for (int i = 0; i < 16; i++) {
            float4 v = rp[i];
            ((float4*)op)[i] = v;
            s += v.x + v.y + v.z + v.w;
        }
        float tot = s + __shfl_xor_sync(0xffffffffu, s, 1);
        if (half == 0) g_pp[((size_t)b * 32 + tile) * CO_ + co] = tot;
    }
}

// ---------------- K5: channel attention MLP ----------------
__global__ void attn_kernel(const float* __restrict__ aw1, const float* __restrict__ ab1,
                            const float* __restrict__ aw2, const float* __restrict__ ab2) {
    int b = blockIdx.x;
    int t = threadIdx.x;  // 256
    __shared__ float pm[CO_], hh[16];
    {
        float s = 0.f;
#pragma unroll
        for (int i = 0; i < 32; i++) s += g_pp[((size_t)b * 32 + i) * CO_ + t];
        pm[t] = s * (1.f / (float)HW_);
    }
    __syncthreads();
    if (t < 16) {
        float a = ab1[t];
        for (int i = 0; i < CO_; i++) a += aw1[t * CO_ + i] * pm[i];
        hh[t] = fmaxf(a, 0.f);
    }
    __syncthreads();
    float a = ab2[t];
#pragma unroll
    for (int j = 0; j < 16; j++) a += aw2[t * 16 + j] * hh[j];
    g_ca[b * CO_ + t] = 1.f / (1.f + expf(-a));
}

// ---------------- K6: in-place output scaling ----------------
__global__ void scale_kernel(float* __restrict__ out) {
    size_t i = (size_t)blockIdx.x * 256 + threadIdx.x;  // float4 index
    float4* o4 = (float4*)out;
    size_t plane = i >> 10;
    float c = g_ca[plane];
    float4 v = o4[i];
    v.x *= c; v.y *= c; v.z *= c; v.w *= c;
    o4[i] = v;
}

// ---------------- launch ----------------
extern "C" void kernel_launch(void* const* d_in, const int* in_sizes, int n_in,
                              void* d_out, int out_size) {
    const float* x       = (const float*)d_in[0];
    const float* experts = (const float*)d_in[1];
    const float* rw1 = (const float*)d_in[2];
    const float* rb1 = (const float*)d_in[3];
    const float* rw2 = (const float*)d_in[4];
    const float* rb2 = (const float*)d_in[5];
    const float* rw3 = (const float*)d_in[6];
    const float* rb3 = (const float*)d_in[7];
    const float* aw1 = (const float*)d_in[8];
    const float* ab1 = (const float*)d_in[9];
    const float* aw2 = (const float*)d_in[10];
    const float* ab2 = (const float*)d_in[11];
    float* out = (float*)d_out;

    cudaFuncSetAttribute(conv_mma_kernel, cudaFuncAttributeMaxDynamicSharedMemorySize,
                         SMEM_TOTAL);

    xprep_kernel<<<B_ * CI_, 256>>>(x);
    routing_kernel<<<B_, 128>>>(rw1, rb1, rw2, rb2, rw3, rb3);
    combine_kernel<<<CO_, 128>>>(experts);
    conv_mma_kernel<<<dim3(32, B_), 512, SMEM_TOTAL>>>(out);
    attn_kernel<<<B_, 256>>>(aw1, ab1, aw2, ab2);
    scale_kernel<<<(B_ * CO_ * HW_ / 4) / 256, 256>>>(out);
}

// round 7
// speedup vs baseline: 4.5382x; 1.0029x over previous
#include <cuda_runtime.h>
#include <cuda_fp16.h>
#include <math.h>
#include <stdint.h>

#define B_  32
#define CI_ 128
#define CO_ 256
#define H_  64
#define W_  64
#define E_  8
#define HW_ 4096
#define XROWS 66
#define XPLANE (XROWS * 64)   // 4224 halves per (kw,b,ci)

// ---------------- scratch ----------------
__device__ float g_pooled[B_ * CI_];
__device__ float g_rw[B_ * E_];
__device__ __half g_x3[(size_t)3 * B_ * CI_ * XPLANE];      // kw-shifted, halo-padded x (fp16)
__device__ __half g_wh[(size_t)B_ * 9 * CO_ * CI_];         // [b][r][co][ci]
__device__ float g_pp[(size_t)B_ * 32 * CO_];               // [b][tile][co]
__device__ float g_ca[B_ * CO_];

// ---------------- PTX helpers (base sm_103 PTX only) ----------------
__device__ __forceinline__ uint32_t smem_u32(const void* p) {
    uint32_t a;
    asm("{ .reg .u64 t; cvta.to.shared.u64 t, %1; cvt.u32.u64 %0, t; }" : "=r"(a) : "l"(p));
    return a;
}
__device__ __forceinline__ void ldsm4(uint32_t* r, uint32_t addr) {
    asm volatile("ldmatrix.sync.aligned.m8n8.x4.shared.b16 {%0,%1,%2,%3}, [%4];"
                 : "=r"(r[0]), "=r"(r[1]), "=r"(r[2]), "=r"(r[3]) : "r"(addr));
}
__device__ __forceinline__ void ldsm4t(uint32_t* r, uint32_t addr) {
    asm volatile("ldmatrix.sync.aligned.m8n8.x4.trans.shared.b16 {%0,%1,%2,%3}, [%4];"
                 : "=r"(r[0]), "=r"(r[1]), "=r"(r[2]), "=r"(r[3]) : "r"(addr));
}
__device__ __forceinline__ void mma_f16(float* d, const uint32_t* a, const uint32_t* b) {
    asm volatile(
        "mma.sync.aligned.m16n8k16.row.col.f32.f16.f16.f32 "
        "{%0,%1,%2,%3}, {%4,%5,%6,%7}, {%8,%9}, {%0,%1,%2,%3};"
        : "+f"(d[0]), "+f"(d[1]), "+f"(d[2]), "+f"(d[3])
        : "r"(a[0]), "r"(a[1]), "r"(a[2]), "r"(a[3]), "r"(b[0]), "r"(b[1]));
}
__device__ __forceinline__ void cp16(uint32_t dst, const void* src) {
    asm volatile("cp.async.cg.shared.global [%0], [%1], 16;" :: "r"(dst), "l"(src) : "memory");
}
#define CP_COMMIT() asm volatile("cp.async.commit_group;" ::: "memory")
#define CP_WAIT2()  asm volatile("cp.async.wait_group 2;" ::: "memory")

// ---------------- K1: x -> fp16 shifted copies + pooled mean ----------------
__global__ __launch_bounds__(256) void xprep_kernel(const float* __restrict__ x) {
    const int bc = blockIdx.x;             // b*CI + ci
    const int b = bc >> 7, ci = bc & 127;
    const int tid = threadIdx.x;
    __shared__ float xp[HW_];
    __shared__ float rs[256];
    const float* src = x + (size_t)bc * HW_;
    float s = 0.f;
    for (int i = tid; i < HW_; i += 256) {
        float v = src[i];
        xp[i] = v;
        s += v;
    }
    rs[tid] = s;
    __syncthreads();
    for (int off = 128; off > 0; off >>= 1) {
        if (tid < off) rs[tid] += rs[tid + off];
        __syncthreads();
    }
    if (tid == 0) g_pooled[bc] = rs[0] * (1.f / (float)HW_);

#pragma unroll
    for (int kw = 0; kw < 3; kw++) {
        __half2* dst = (__half2*)(g_x3 + ((size_t)(kw * B_ + b) * CI_ + ci) * XPLANE);
        for (int idx = tid; idx < XROWS * 32; idx += 256) {
            int row = idx >> 5;            // 0..65 (= gy+1)
            int px = (idx & 31) * 2;
            int gy = row - 1;
            float v0 = 0.f, v1 = 0.f;
            if ((unsigned)gy < (unsigned)H_) {
                int gx0 = px + kw - 1;
                int gx1 = gx0 + 1;
                if ((unsigned)gx0 < (unsigned)W_) v0 = xp[gy * 64 + gx0];
                if ((unsigned)gx1 < (unsigned)W_) v1 = xp[gy * 64 + gx1];
            }
            dst[idx] = __floats2half2_rn(v0, v1);
        }
    }
}

// ---------------- K2: routing MLP + softmax ----------------
__global__ void routing_kernel(const float* __restrict__ rw1, const float* __restrict__ rb1,
                               const float* __restrict__ rw2, const float* __restrict__ rb2,
                               const float* __restrict__ rw3, const float* __restrict__ rb3) {
    int b = blockIdx.x;
    int t = threadIdx.x;  // 128
    __shared__ float pl[CI_], h[E_], s[CI_], lg[E_];
    pl[t] = g_pooled[b * CI_ + t];
    __syncthreads();
    if (t < E_) {
        float a = rb1[t];
        for (int i = 0; i < CI_; i++) a += rw1[t * CI_ + i] * pl[i];
        h[t] = fmaxf(a, 0.f);
    }
    __syncthreads();
    {
        float a = rb2[t];
#pragma unroll
        for (int j = 0; j < E_; j++) a += rw2[t * E_ + j] * h[j];
        s[t] = 1.f / (1.f + expf(-a));
    }
    __syncthreads();
    if (t < E_) {
        float a = rb3[t];
        for (int i = 0; i < CI_; i++) a += rw3[t * CI_ + i] * s[i];
        lg[t] = a;
    }
    __syncthreads();
    if (t == 0) {
        float m = lg[0];
        for (int e = 1; e < E_; e++) m = fmaxf(m, lg[e]);
        float den = 0.f, ex[E_];
        for (int e = 0; e < E_; e++) { ex[e] = expf(lg[e] - m); den += ex[e]; }
        float inv = 1.f / den;
        for (int e = 0; e < E_; e++) g_rw[b * E_ + e] = ex[e] * inv;
    }
}

// ---------------- K3: combine experts -> fp16 [b][r][co][ci] -----------------
__global__ void combine_kernel(const float* __restrict__ experts) {
    int co = blockIdx.x;   // 256
    int ci = threadIdx.x;  // 128
    __shared__ float rws[B_ * E_];
    rws[ci] = g_rw[ci];
    rws[ci + 128] = g_rw[ci + 128];
    __syncthreads();
    float ex[E_ * 9];
#pragma unroll
    for (int e = 0; e < E_; e++) {
        const float* p = experts + (((size_t)e * CO_ + co) * CI_ + ci) * 9;
#pragma unroll
        for (int r = 0; r < 9; r++) ex[e * 9 + r] = p[r];
    }
    for (int b = 0; b < B_; b++) {
#pragma unroll
        for (int r = 0; r < 9; r++) {
            float acc = 0.f;
#pragma unroll
            for (int e = 0; e < E_; e++) acc += rws[b * E_ + e] * ex[e * 9 + r];
            g_wh[((size_t)(b * 9 + r) * CO_ + co) * CI_ + ci] = __float2half_rn(acc);
        }
    }
}

// ---------------- K4: implicit-GEMM conv (fp16, 8 warps, 64x64 warp tile) ----
// grid (32 pixel-tiles, 32 b), 256 threads, warp grid 2(M)x4(N).
// M=128 pixels, N=256 co, K=1152 over 18 stages of 64 ci, 4-stage cp.async ring.
#define OFF_A  0
#define OFF_B  16384
#define BUFB   49152
#define NSTAGE 4
#define SMEM_TOTAL (NSTAGE * BUFB)  // 196608

__global__ __launch_bounds__(256, 1) void conv_mma_kernel(float* __restrict__ out) {
    extern __shared__ char smem[];
    const uint32_t sb = smem_u32(smem);
    const int tid = threadIdx.x;
    const int wid = tid >> 5;
    const int lane = tid & 31;
    const int tile = blockIdx.x;
    const int b = blockIdx.y;
    const int warp_m = wid & 1;   // 0..1 -> 64-pixel chunk
    const int warp_n = wid >> 1;  // 0..3 -> 64-co chunk

    float d[4][8][4];
#pragma unroll
    for (int i = 0; i < 4; i++)
#pragma unroll
        for (int j = 0; j < 8; j++)
#pragma unroll
            for (int q = 0; q < 4; q++) d[i][j][q] = 0.f;

    const __half* whb = g_wh + (size_t)b * 9 * CO_ * CI_;

    auto stage = [&](int s) {
        const int r = s >> 1;
        const int ci0 = (s & 1) * 64;
        const int kh = r / 3, kw = r - kh * 3;
        const uint32_t base = sb + (uint32_t)((s & 3) * BUFB);
        // A: 64 ci rows x 128 px (2 gmem rows) fp16
        const char* asrc = (const char*)(g_x3 + ((size_t)(kw * B_ + b) * CI_ + ci0) * XPLANE +
                                         (size_t)(tile * 2 + kh) * 64);
#pragma unroll
        for (int it = 0; it < 4; it++) {
            int idx = tid + it * 256;
            int ci = idx >> 4, ch = idx & 15;
            cp16(base + OFF_A + (uint32_t)(ci * 256 + ((ch * 16) ^ ((ci & 7) << 4))),
                 asrc + (size_t)ci * (XPLANE * 2) + ch * 16);
        }
        // B: 256 co x 64 ci fp16
        const char* hsrc = (const char*)(whb + (size_t)r * CO_ * CI_ + ci0);
#pragma unroll
        for (int it = 0; it < 8; it++) {
            int idx = tid + it * 256;
            int co = idx >> 3, ch = idx & 7;
            uint32_t off = (uint32_t)(co * 128 + ((ch * 16) ^ ((co & 7) << 4)));
            cp16(base + OFF_B + off, hsrc + (size_t)co * 256 + ch * 16);
        }
        CP_COMMIT();
    };

    stage(0);
    stage(1);
    stage(2);

    // ldmatrix lane components
    const int a_t = lane >> 3, a_rl = lane & 7;               // A x4 trans
    const int b_q = lane >> 3, b_rl = lane & 7;               // B x4
    const int b_nsel = b_q >> 1, b_ksel = b_q & 1;

    for (int s = 0; s < 18; s++) {
        CP_WAIT2();
        __syncthreads();
        if (s < 15) stage(s + 3);
        const uint32_t cur = sb + (uint32_t)((s & 3) * BUFB);

#pragma unroll
        for (int kc = 0; kc < 4; kc++) {
            uint32_t ah[4][4];
#pragma unroll
            for (int mi = 0; mi < 4; mi++) {
                int k_row = kc * 16 + (a_t >> 1) * 8 + a_rl;
                int m_col = warp_m * 64 + mi * 16 + (a_t & 1) * 8;
                uint32_t addr = cur + OFF_A +
                                (uint32_t)(k_row * 256 + ((m_col * 2) ^ (a_rl << 4)));
                ldsm4t(ah[mi], addr);
            }
#pragma unroll
            for (int njp = 0; njp < 4; njp++) {
                int n = warp_n * 64 + njp * 16 + b_nsel * 8 + b_rl;
                uint32_t kb = (uint32_t)(kc * 32 + b_ksel * 16);
                uint32_t off = (uint32_t)(n * 128) + (kb ^ (uint32_t)(b_rl << 4));
                uint32_t bh[4];
                ldsm4(bh, cur + OFF_B + off);
#pragma unroll
                for (int j = 0; j < 2; j++)
#pragma unroll
                    for (int mi = 0; mi < 4; mi++)
                        mma_f16(d[mi][njp * 2 + j], ah[mi], bh + 2 * j);
            }
        }
    }

    // ---- epilogue: transpose through smem (stride 132 = 16B-periodic) ----
    __syncthreads();
    float* red = (float*)smem;  // [256 co][132] = 135168 B
#pragma unroll
    for (int mi = 0; mi < 4; mi++)
#pragma unroll
        for (int ni = 0; ni < 8; ni++) {
            int m = warp_m * 64 + mi * 16 + (lane >> 2);
            int n = warp_n * 64 + ni * 8 + 2 * (lane & 3);
            const float* a = d[mi][ni];
            red[n * 132 + m] = a[0];
            red[(n + 1) * 132 + m] = a[1];
            red[n * 132 + m + 8] = a[2];
            red[(n + 1) * 132 + m + 8] = a[3];
        }
    __syncthreads();
    // writeout: 4 threads per co row (q = px quarter), 128B-coalesced stores
    {
        const int q = tid & 3;
        float psum[4];
#pragma unroll
        for (int g = 0; g < 4; g++) {
            int co = g * 64 + (tid >> 2);
            const float* rp = red + co * 132 + q * 32;
            float* op = out + ((size_t)(b * CO_ + co)) * HW_ + tile * 128 + q * 32;
            float s = 0.f;
#pragma unroll
            for (int i = 0; i < 8; i++) {
                float4 v = *(const float4*)(rp + i * 4);
                ((float4*)op)[i] = v;
                s += v.x + v.y + v.z + v.w;
            }
            psum[g] = s;
        }
#pragma unroll
        for (int g = 0; g < 4; g++) {
            float tot = psum[g];
            tot += __shfl_xor_sync(0xffffffffu, tot, 1);
            tot += __shfl_xor_sync(0xffffffffu, tot, 2);
            if (q == 0) {
                int co = g * 64 + (tid >> 2);
                g_pp[((size_t)b * 32 + tile) * CO_ + co] = tot;
            }
        }
    }
}

// ---------------- K5: channel attention MLP ----------------
__global__ void attn_kernel(const float* __restrict__ aw1, const float* __restrict__ ab1,
                            const float* __restrict__ aw2, const float* __restrict__ ab2) {
    int b = blockIdx.x;
    int t = threadIdx.x;  // 256
    __shared__ float pm[CO_], hh[16];
    {
        float s = 0.f;
#pragma unroll
        for (int i = 0; i < 32; i++) s += g_pp[((size_t)b * 32 + i) * CO_ + t];
        pm[t] = s * (1.f / (float)HW_);
    }
    __syncthreads();
    if (t < 16) {
        float a = ab1[t];
        for (int i = 0; i < CO_; i++) a += aw1[t * CO_ + i] * pm[i];
        hh[t] = fmaxf(a, 0.f);
    }
    __syncthreads();
    float a = ab2[t];
#pragma unroll
    for (int j = 0; j < 16; j++) a += aw2[t * 16 + j] * hh[j];
    g_ca[b * CO_ + t] = 1.f / (1.f + expf(-a));
}

// ---------------- K6: in-place output scaling ----------------
__global__ void scale_kernel(float* __restrict__ out) {
    size_t i = (size_t)blockIdx.x * 256 + threadIdx.x;  // float4 index
    float4* o4 = (float4*)out;
    size_t plane = i >> 10;
    float c = g_ca[plane];
    float4 v = o4[i];
    v.x *= c; v.y *= c; v.z *= c; v.w *= c;
    o4[i] = v;
}

// ---------------- launch ----------------
extern "C" void kernel_launch(void* const* d_in, const int* in_sizes, int n_in,
                              void* d_out, int out_size) {
    const float* x       = (const float*)d_in[0];
    const float* experts = (const float*)d_in[1];
    const float* rw1 = (const float*)d_in[2];
    const float* rb1 = (const float*)d_in[3];
    const float* rw2 = (const float*)d_in[4];
    const float* rb2 = (const float*)d_in[5];
    const float* rw3 = (const float*)d_in[6];
    const float* rb3 = (const float*)d_in[7];
    const float* aw1 = (const float*)d_in[8];
    const float* ab1 = (const float*)d_in[9];
    const float* aw2 = (const float*)d_in[10];
    const float* ab2 = (const float*)d_in[11];
    float* out = (float*)d_out;

    cudaFuncSetAttribute(conv_mma_kernel, cudaFuncAttributeMaxDynamicSharedMemorySize,
                         SMEM_TOTAL);

    xprep_kernel<<<B_ * CI_, 256>>>(x);
    routing_kernel<<<B_, 128>>>(rw1, rb1, rw2, rb2, rw3, rb3);
    combine_kernel<<<CO_, 128>>>(experts);
    conv_mma_kernel<<<dim3(32, B_), 256, SMEM_TOTAL>>>(out);
    attn_kernel<<<B_, 256>>>(aw1, ab1, aw2, ab2);
    scale_kernel<<<(B_ * CO_ * HW_ / 4) / 256, 256>>>(out);
}

// round 8
// speedup vs baseline: 4.7243x; 1.0410x over previous
#include <cuda_runtime.h>
#include <cuda_fp16.h>
#include <math.h>
#include <stdint.h>

#define B_  32
#define CI_ 128
#define CO_ 256
#define H_  64
#define W_  64
#define E_  8
#define HW_ 4096
#define XROWS 66
#define XPLANE (XROWS * 64)   // 4224 halves per (kw,b,ci)

// ---------------- scratch ----------------
__device__ float g_pooled[B_ * CI_];
__device__ float g_rw[B_ * E_];
__device__ __half g_x3[(size_t)3 * B_ * CI_ * XPLANE];      // kw-shifted, halo-padded x (fp16)
__device__ __half g_wh[(size_t)B_ * 9 * CO_ * CI_];         // [b][r][co][ci]
__device__ float g_pp[(size_t)B_ * 32 * CO_];               // [b][tile][co]
__device__ float g_ca[B_ * CO_];

// ---------------- PTX helpers (base sm_103 PTX only) ----------------
__device__ __forceinline__ uint32_t smem_u32(const void* p) {
    uint32_t a;
    asm("{ .reg .u64 t; cvta.to.shared.u64 t, %1; cvt.u32.u64 %0, t; }" : "=r"(a) : "l"(p));
    return a;
}
__device__ __forceinline__ void ldsm4(uint32_t* r, uint32_t addr) {
    asm volatile("ldmatrix.sync.aligned.m8n8.x4.shared.b16 {%0,%1,%2,%3}, [%4];"
                 : "=r"(r[0]), "=r"(r[1]), "=r"(r[2]), "=r"(r[3]) : "r"(addr));
}
__device__ __forceinline__ void ldsm4t(uint32_t* r, uint32_t addr) {
    asm volatile("ldmatrix.sync.aligned.m8n8.x4.trans.shared.b16 {%0,%1,%2,%3}, [%4];"
                 : "=r"(r[0]), "=r"(r[1]), "=r"(r[2]), "=r"(r[3]) : "r"(addr));
}
__device__ __forceinline__ void mma_f16(float* d, const uint32_t* a, const uint32_t* b) {
    asm volatile(
        "mma.sync.aligned.m16n8k16.row.col.f32.f16.f16.f32 "
        "{%0,%1,%2,%3}, {%4,%5,%6,%7}, {%8,%9}, {%0,%1,%2,%3};"
        : "+f"(d[0]), "+f"(d[1]), "+f"(d[2]), "+f"(d[3])
        : "r"(a[0]), "r"(a[1]), "r"(a[2]), "r"(a[3]), "r"(b[0]), "r"(b[1]));
}
__device__ __forceinline__ void cp16(uint32_t dst, const void* src) {
    asm volatile("cp.async.cg.shared.global [%0], [%1], 16;" :: "r"(dst), "l"(src) : "memory");
}
#define CP_COMMIT() asm volatile("cp.async.commit_group;" ::: "memory")
#define CP_WAIT1()  asm volatile("cp.async.wait_group 1;" ::: "memory")

// ---------------- K1: x -> fp16 shifted copies + pooled mean ----------------
__global__ __launch_bounds__(256) void xprep_kernel(const float* __restrict__ x) {
    const int bc = blockIdx.x;             // b*CI + ci
    const int b = bc >> 7, ci = bc & 127;
    const int tid = threadIdx.x;
    __shared__ float xp[HW_];
    __shared__ float rs[256];
    const float* src = x + (size_t)bc * HW_;
    float s = 0.f;
    for (int i = tid; i < HW_; i += 256) {
        float v = src[i];
        xp[i] = v;
        s += v;
    }
    rs[tid] = s;
    __syncthreads();
    for (int off = 128; off > 0; off >>= 1) {
        if (tid < off) rs[tid] += rs[tid + off];
        __syncthreads();
    }
    if (tid == 0) g_pooled[bc] = rs[0] * (1.f / (float)HW_);

#pragma unroll
    for (int kw = 0; kw < 3; kw++) {
        __half2* dst = (__half2*)(g_x3 + ((size_t)(kw * B_ + b) * CI_ + ci) * XPLANE);
        for (int idx = tid; idx < XROWS * 32; idx += 256) {
            int row = idx >> 5;            // 0..65 (= gy+1)
            int px = (idx & 31) * 2;
            int gy = row - 1;
            float v0 = 0.f, v1 = 0.f;
            if ((unsigned)gy < (unsigned)H_) {
                int gx0 = px + kw - 1;
                int gx1 = gx0 + 1;
                if ((unsigned)gx0 < (unsigned)W_) v0 = xp[gy * 64 + gx0];
                if ((unsigned)gx1 < (unsigned)W_) v1 = xp[gy * 64 + gx1];
            }
            dst[idx] = __floats2half2_rn(v0, v1);
        }
    }
}

// ---------------- K2: routing MLP + softmax ----------------
__global__ void routing_kernel(const float* __restrict__ rw1, const float* __restrict__ rb1,
                               const float* __restrict__ rw2, const float* __restrict__ rb2,
                               const float* __restrict__ rw3, const float* __restrict__ rb3) {
    int b = blockIdx.x;
    int t = threadIdx.x;  // 128
    __shared__ float pl[CI_], h[E_], s[CI_], lg[E_];
    pl[t] = g_pooled[b * CI_ + t];
    __syncthreads();
    if (t < E_) {
        float a = rb1[t];
        for (int i = 0; i < CI_; i++) a += rw1[t * CI_ + i] * pl[i];
        h[t] = fmaxf(a, 0.f);
    }
    __syncthreads();
    {
        float a = rb2[t];
#pragma unroll
        for (int j = 0; j < E_; j++) a += rw2[t * E_ + j] * h[j];
        s[t] = 1.f / (1.f + expf(-a));
    }
    __syncthreads();
    if (t < E_) {
        float a = rb3[t];
        for (int i = 0; i < CI_; i++) a += rw3[t * CI_ + i] * s[i];
        lg[t] = a;
    }
    __syncthreads();
    if (t == 0) {
        float m = lg[0];
        for (int e = 1; e < E_; e++) m = fmaxf(m, lg[e]);
        float den = 0.f, ex[E_];
        for (int e = 0; e < E_; e++) { ex[e] = expf(lg[e] - m); den += ex[e]; }
        float inv = 1.f / den;
        for (int e = 0; e < E_; e++) g_rw[b * E_ + e] = ex[e] * inv;
    }
}

// ---------------- K3: combine experts -> fp16 [b][r][co][ci] -----------------
__global__ void combine_kernel(const float* __restrict__ experts) {
    int co = blockIdx.x;   // 256
    int ci = threadIdx.x;  // 128
    __shared__ float rws[B_ * E_];
    rws[ci] = g_rw[ci];
    rws[ci + 128] = g_rw[ci + 128];
    __syncthreads();
    float ex[E_ * 9];
#pragma unroll
    for (int e = 0; e < E_; e++) {
        const float* p = experts + (((size_t)e * CO_ + co) * CI_ + ci) * 9;
#pragma unroll
        for (int r = 0; r < 9; r++) ex[e * 9 + r] = p[r];
    }
    for (int b = 0; b < B_; b++) {
#pragma unroll
        for (int r = 0; r < 9; r++) {
            float acc = 0.f;
#pragma unroll
            for (int e = 0; e < E_; e++) acc += rws[b * E_ + e] * ex[e * 9 + r];
            g_wh[((size_t)(b * 9 + r) * CO_ + co) * CI_ + ci] = __float2half_rn(acc);
        }
    }
}

// ---------------- K4: implicit-GEMM conv (fp16, M128xN128 CTA, 2 CTA/SM) -----
// grid (32 pixel-tiles, 2 co-halves, 32 b), 256 threads, warp grid 4(M)x2(N),
// warp tile 32x64. K=1152 over 18 stages of 64 ci, 3-stage cp.async ring.
#define OFF_A  0
#define OFF_B  16384
#define BUFB   32768
#define NSTAGE 3
#define SMEM_TOTAL (NSTAGE * BUFB)  // 98304

__global__ __launch_bounds__(256, 2) void conv_mma_kernel(float* __restrict__ out) {
    extern __shared__ char smem[];
    const uint32_t sb = smem_u32(smem);
    const int tid = threadIdx.x;
    const int wid = tid >> 5;
    const int lane = tid & 31;
    const int tile = blockIdx.x;
    const int nhalf = blockIdx.y;
    const int b = blockIdx.z;
    const int warp_m = wid & 3;   // 0..3 -> 32-pixel chunk
    const int warp_n = wid >> 2;  // 0..1 -> 64-co chunk

    float d[2][8][4];
#pragma unroll
    for (int i = 0; i < 2; i++)
#pragma unroll
        for (int j = 0; j < 8; j++)
#pragma unroll
            for (int q = 0; q < 4; q++) d[i][j][q] = 0.f;

    const __half* whb = g_wh + (size_t)b * 9 * CO_ * CI_ + (size_t)nhalf * 128 * CI_;

    auto stage = [&](int s) {
        const int r = s >> 1;
        const int ci0 = (s & 1) * 64;
        const int kh = r / 3, kw = r - kh * 3;
        const int slot = s % NSTAGE;
        const uint32_t base = sb + (uint32_t)(slot * BUFB);
        // A: 64 ci rows x 128 px (2 gmem rows) fp16 = 16 KB
        const char* asrc = (const char*)(g_x3 + ((size_t)(kw * B_ + b) * CI_ + ci0) * XPLANE +
                                         (size_t)(tile * 2 + kh) * 64);
#pragma unroll
        for (int it = 0; it < 4; it++) {
            int idx = tid + it * 256;
            int ci = idx >> 4, ch = idx & 15;
            cp16(base + OFF_A + (uint32_t)(ci * 256 + ((ch * 16) ^ ((ci & 7) << 4))),
                 asrc + (size_t)ci * (XPLANE * 2) + ch * 16);
        }
        // B: 128 co x 64 ci fp16 = 16 KB
        const char* hsrc = (const char*)(whb + (size_t)r * CO_ * CI_ + ci0);
#pragma unroll
        for (int it = 0; it < 4; it++) {
            int idx = tid + it * 256;
            int co = idx >> 3, ch = idx & 7;
            uint32_t off = (uint32_t)(co * 128 + ((ch * 16) ^ ((co & 7) << 4)));
            cp16(base + OFF_B + off, hsrc + (size_t)co * 256 + ch * 16);
        }
        CP_COMMIT();
    };

    stage(0);
    stage(1);

    // ldmatrix lane components
    const int a_t = lane >> 3, a_rl = lane & 7;               // A x4 trans
    const int b_q = lane >> 3, b_rl = lane & 7;               // B x4
    const int b_nsel = b_q >> 1, b_ksel = b_q & 1;

    for (int s = 0; s < 18; s++) {
        CP_WAIT1();
        __syncthreads();
        if (s < 16) stage(s + 2);
        const uint32_t cur = sb + (uint32_t)((s % NSTAGE) * BUFB);

#pragma unroll
        for (int kc = 0; kc < 4; kc++) {
            uint32_t ah[2][4];
#pragma unroll
            for (int mi = 0; mi < 2; mi++) {
                int k_row = kc * 16 + (a_t >> 1) * 8 + a_rl;
                int m_col = warp_m * 32 + mi * 16 + (a_t & 1) * 8;
                uint32_t addr = cur + OFF_A +
                                (uint32_t)(k_row * 256 + ((m_col * 2) ^ (a_rl << 4)));
                ldsm4t(ah[mi], addr);
            }
#pragma unroll
            for (int njp = 0; njp < 4; njp++) {
                int n = warp_n * 64 + njp * 16 + b_nsel * 8 + b_rl;
                uint32_t kb = (uint32_t)(kc * 32 + b_ksel * 16);
                uint32_t off = (uint32_t)(n * 128) + (kb ^ (uint32_t)(b_rl << 4));
                uint32_t bh[4];
                ldsm4(bh, cur + OFF_B + off);
#pragma unroll
                for (int j = 0; j < 2; j++)
#pragma unroll
                    for (int mi = 0; mi < 2; mi++)
                        mma_f16(d[mi][njp * 2 + j], ah[mi], bh + 2 * j);
            }
        }
    }

    // ---- epilogue: transpose through smem (stride 132 = 16B-periodic) ----
    __syncthreads();
    float* red = (float*)smem;  // [128 co][132] = 67584 B
#pragma unroll
    for (int mi = 0; mi < 2; mi++)
#pragma unroll
        for (int ni = 0; ni < 8; ni++) {
            int m = warp_m * 32 + mi * 16 + (lane >> 2);
            int n = warp_n * 64 + ni * 8 + 2 * (lane & 3);
            const float* a = d[mi][ni];
            red[n * 132 + m] = a[0];
            red[(n + 1) * 132 + m] = a[1];
            red[n * 132 + m + 8] = a[2];
            red[(n + 1) * 132 + m + 8] = a[3];
        }
    __syncthreads();
    {
        int col = tid >> 1, half = tid & 1;       // col 0..127 local
        int co = nhalf * 128 + col;
        const float4* rp = (const float4*)(red + col * 132 + half * 64);
        float* op = out + ((size_t)(b * CO_ + co)) * HW_ + tile * 128 + half * 64;
        float s = 0.f;
#pragma unroll
        for (int i = 0; i < 16; i++) {
            float4 v = rp[i];
            ((float4*)op)[i] = v;
            s += v.x + v.y + v.z + v.w;
        }
        float tot = s + __shfl_xor_sync(0xffffffffu, s, 1);
        if (half == 0) g_pp[((size_t)b * 32 + tile) * CO_ + co] = tot;
    }
}

// ---------------- K5: channel attention MLP ----------------
__global__ void attn_kernel(const float* __restrict__ aw1, const float* __restrict__ ab1,
                            const float* __restrict__ aw2, const float* __restrict__ ab2) {
    int b = blockIdx.x;
    int t = threadIdx.x;  // 256
    __shared__ float pm[CO_], hh[16];
    {
        float s = 0.f;
#pragma unroll
        for (int i = 0; i < 32; i++) s += g_pp[((size_t)b * 32 + i) * CO_ + t];
        pm[t] = s * (1.f / (float)HW_);
    }
    __syncthreads();
    if (t < 16) {
        float a = ab1[t];
        for (int i = 0; i < CO_; i++) a += aw1[t * CO_ + i] * pm[i];
        hh[t] = fmaxf(a, 0.f);
    }
    __syncthreads();
    float a = ab2[t];
#pragma unroll
    for (int j = 0; j < 16; j++) a += aw2[t * 16 + j] * hh[j];
    g_ca[b * CO_ + t] = 1.f / (1.f + expf(-a));
}

// ---------------- K6: in-place output scaling ----------------
__global__ void scale_kernel(float* __restrict__ out) {
    size_t i = (size_t)blockIdx.x * 256 + threadIdx.x;  // float4 index
    float4* o4 = (float4*)out;
    size_t plane = i >> 10;
    float c = g_ca[plane];
    float4 v = o4[i];
    v.x *= c; v.y *= c; v.z *= c; v.w *= c;
    o4[i] = v;
}

// ---------------- launch ----------------
extern "C" void kernel_launch(void* const* d_in, const int* in_sizes, int n_in,
                              void* d_out, int out_size) {
    const float* x       = (const float*)d_in[0];
    const float* experts = (const float*)d_in[1];
    const float* rw1 = (const float*)d_in[2];
    const float* rb1 = (const float*)d_in[3];
    const float* rw2 = (const float*)d_in[4];
    const float* rb2 = (const float*)d_in[5];
    const float* rw3 = (const float*)d_in[6];
    const float* rb3 = (const float*)d_in[7];
    const float* aw1 = (const float*)d_in[8];
    const float* ab1 = (const float*)d_in[9];
    const float* aw2 = (const float*)d_in[10];
    const float* ab2 = (const float*)d_in[11];
    float* out = (float*)d_out;

    cudaFuncSetAttribute(conv_mma_kernel, cudaFuncAttributeMaxDynamicSharedMemorySize,
                         SMEM_TOTAL);

    xprep_kernel<<<B_ * CI_, 256>>>(x);
    routing_kernel<<<B_, 128>>>(rw1, rb1, rw2, rb2, rw3, rb3);
    combine_kernel<<<CO_, 128>>>(experts);
    conv_mma_kernel<<<dim3(32, 2, B_), 256, SMEM_TOTAL>>>(out);
    attn_kernel<<<B_, 256>>>(aw1, ab1, aw2, ab2);
    scale_kernel<<<(B_ * CO_ * HW_ / 4) / 256, 256>>>(out);
}